// round 2
// baseline (speedup 1.0000x reference)
#include <cuda_runtime.h>
#include <math.h>

// Problem constants
#define HID 1024
#define NE 64
#define ROWS 32          // BIG*INNER rows per expert
#define KC 128           // hidden-dim chunk staged in smem
#define NK (HID / KC)    // 8 chunks
#define MAXBS 1024

// ---- device scratch (no allocs allowed) ----
__device__ int g_count[NE];
__device__ int g_pairs[NE * MAXBS];   // packed token*4 + slot
__device__ int g_ids[MAXBS * 12];     // per-token candidate ids (masked = -10000)

__global__ void init_kernel() {
    if (threadIdx.x < NE) g_count[threadIdx.x] = 0;
}

// ============================================================
// Phase A: router GEMM (8 tokens/block), top-4 + renorm weights,
// writes final_weights directly, buckets (token,slot) pairs per expert.
// ============================================================
__global__ __launch_bounds__(256) void phaseA(const float* __restrict__ x,
                                              const float* __restrict__ wg,
                                              float* __restrict__ outw,
                                              int bs, int write_w) {
    __shared__ float4 ws4[NE][KC / 4 + 1];   // +1 pad: conflict-free LDS.128
    __shared__ float4 xs4[8][KC / 4 + 1];
    __shared__ float  lg[8][NE + 1];

    int t  = threadIdx.x;
    int r  = t & 63;      // expert row 0..63
    int tg = t >> 6;      // token group 0..3 -> tokens tg, tg+4
    int tok0 = blockIdx.x * 8;

    float acc0 = 0.f, acc1 = 0.f;
    for (int c = 0; c < NK; ++c) {
        // stage router weights: 64 x 32 float4
        #pragma unroll
        for (int i = 0; i < 8; ++i) {
            int idx = t + i * 256;
            int row = idx >> 5, col = idx & 31;
            ws4[row][col] =
                reinterpret_cast<const float4*>(wg)[row * (HID / 4) + c * (KC / 4) + col];
        }
        // stage x tile: 8 x 32 float4
        {
            int row = t >> 5, col = t & 31;
            int tok = tok0 + row;
            float4 v = make_float4(0.f, 0.f, 0.f, 0.f);
            if (tok < bs)
                v = reinterpret_cast<const float4*>(x)[tok * (HID / 4) + c * (KC / 4) + col];
            xs4[row][col] = v;
        }
        __syncthreads();
        #pragma unroll
        for (int k = 0; k < KC / 4; ++k) {
            float4 w = ws4[r][k];
            float4 a = xs4[tg][k];
            float4 b = xs4[tg + 4][k];
            acc0 += w.x * a.x + w.y * a.y + w.z * a.z + w.w * a.w;
            acc1 += w.x * b.x + w.y * b.y + w.z * b.z + w.w * b.w;
        }
        __syncthreads();
    }
    lg[tg][r]     = acc0;
    lg[tg + 4][r] = acc1;
    __syncthreads();

    if (t < 8) {
        int token = tok0 + t;
        if (token < bs) {
            unsigned long long used = 0ULL;
            int sel[4]; float lv[4];
            #pragma unroll
            for (int s = 0; s < 4; ++s) {
                float best = -INFINITY; int bi = 0;
                for (int e = 0; e < NE; ++e) {
                    if ((used >> e) & 1ULL) continue;
                    float v = lg[t][e];
                    if (v > best) { best = v; bi = e; }   // strict > : lowest index wins ties
                }
                used |= 1ULL << bi;
                sel[s] = bi; lv[s] = best;
            }
            // renormalized softmax over selected 4 (full denominator cancels)
            float m  = lv[0];
            float w0 = 1.f;
            float w1 = expf(lv[1] - m);
            float w2 = expf(lv[2] - m);
            float w3 = expf(lv[3] - m);
            float z  = w0 + w1 + w2 + w3;
            w0 /= z; w1 /= z; w2 /= z; w3 /= z;
            if (write_w) {
                float* o = outw + token * 8;
                o[0] = w0; o[1] = w0; o[2] = w0;
                o[3] = w1; o[4] = w1;
                o[5] = w2; o[6] = w2;
                o[7] = w3;
            }
            #pragma unroll
            for (int s = 0; s < 4; ++s) {
                int e   = sel[s];
                int pos = atomicAdd(&g_count[e], 1);
                g_pairs[e * MAXBS + pos] = token * 4 + s;
            }
        }
    }
}

// ============================================================
// Phase B: per-expert grouped gate/up matvecs (16 tokens/block),
// silu-gated scores, inner top-3, pattern-masked id staging.
// ============================================================
__global__ __launch_bounds__(256) void phaseB(const float* __restrict__ x,
                                              const float* __restrict__ gw,
                                              const float* __restrict__ uw) {
    int e   = blockIdx.x;
    int cnt = g_count[e];

    __shared__ float4 ws4[64][KC / 4 + 1];   // rows 0..31 gate, 32..63 up
    __shared__ float4 xs4[16][KC / 4 + 1];
    __shared__ float  res[16][64 + 1];
    __shared__ int    toks[16];

    int t  = threadIdx.x;
    int r  = t & 63;
    int tg = t >> 6;   // tokens tg, tg+4, tg+8, tg+12
    const float* wbg = gw + (size_t)e * ROWS * HID;
    const float* wbu = uw + (size_t)e * ROWS * HID;

    for (int chunk = blockIdx.y; chunk * 16 < cnt; chunk += gridDim.y) {
        int base = chunk * 16;
        if (t < 16) toks[t] = (base + t < cnt) ? g_pairs[e * MAXBS + base + t] : -1;
        __syncthreads();

        float a0 = 0.f, a1 = 0.f, a2 = 0.f, a3 = 0.f;
        for (int c = 0; c < NK; ++c) {
            // stage expert weights: 64 x 32 float4
            #pragma unroll
            for (int i = 0; i < 8; ++i) {
                int idx = t + i * 256;
                int row = idx >> 5, col = idx & 31;
                const float* src = (row < 32) ? (wbg + row * HID) : (wbu + (row - 32) * HID);
                ws4[row][col] = reinterpret_cast<const float4*>(src)[c * (KC / 4) + col];
            }
            // stage gathered x: 16 x 32 float4
            #pragma unroll
            for (int i = 0; i < 2; ++i) {
                int idx = t + i * 256;
                int row = idx >> 5, col = idx & 31;
                int pr = toks[row];
                float4 v = make_float4(0.f, 0.f, 0.f, 0.f);
                if (pr >= 0)
                    v = reinterpret_cast<const float4*>(x)[(pr >> 2) * (HID / 4) + c * (KC / 4) + col];
                xs4[row][col] = v;
            }
            __syncthreads();
            #pragma unroll
            for (int k = 0; k < KC / 4; ++k) {
                float4 w  = ws4[r][k];
                float4 v0 = xs4[tg][k];
                float4 v1 = xs4[tg + 4][k];
                float4 v2 = xs4[tg + 8][k];
                float4 v3 = xs4[tg + 12][k];
                a0 += w.x * v0.x + w.y * v0.y + w.z * v0.z + w.w * v0.w;
                a1 += w.x * v1.x + w.y * v1.y + w.z * v1.z + w.w * v1.w;
                a2 += w.x * v2.x + w.y * v2.y + w.z * v2.z + w.w * v2.w;
                a3 += w.x * v3.x + w.y * v3.y + w.z * v3.z + w.w * v3.w;
            }
            __syncthreads();
        }
        res[tg][r]      = a0;
        res[tg + 4][r]  = a1;
        res[tg + 8][r]  = a2;
        res[tg + 12][r] = a3;
        __syncthreads();

        if (t < 16 && toks[t] >= 0) {
            int pr    = toks[t];
            int token = pr >> 2;
            int slot  = pr & 3;
            float inner[8];
            #pragma unroll
            for (int i = 0; i < 8; ++i) {
                float s = 0.f;
                #pragma unroll
                for (int b = 0; b < 4; ++b) {
                    int j   = i * 4 + b;
                    float g = res[t][j];
                    float u = res[t][32 + j];
                    float sil = g / (1.f + expf(-g));   // silu
                    s += fabsf(u * sil);
                }
                inner[i] = s * 0.25f;
            }
            int keep = (slot == 0) ? 3 : ((slot == 3) ? 1 : 2);  // pattern (3,2,2,1)
            int outb = token * 12 + slot * 3;
            unsigned used = 0;
            #pragma unroll
            for (int jj = 0; jj < 3; ++jj) {
                float best = -INFINITY; int bi = 0;
                #pragma unroll
                for (int i = 0; i < 8; ++i) {
                    if ((used >> i) & 1u) continue;
                    if (inner[i] > best) { best = inner[i]; bi = i; }
                }
                used |= 1u << bi;
                g_ids[outb + jj] = (jj < keep) ? (e * 8 + bi) : -10000;
            }
        }
        __syncthreads();
    }
}

// ============================================================
// Phase C: per-token sort of 12 masked ids, emit top-8 as float.
// ============================================================
__global__ void phaseC(float* __restrict__ out, int bs) {
    int token = blockIdx.x * blockDim.x + threadIdx.x;
    if (token >= bs) return;
    int v[12];
    #pragma unroll
    for (int i = 0; i < 12; ++i) v[i] = g_ids[token * 12 + i];
    #pragma unroll
    for (int i = 1; i < 12; ++i) {      // insertion sort, descending
        int key = v[i], j = i - 1;
        while (j >= 0 && v[j] < key) { v[j + 1] = v[j]; --j; }
        v[j + 1] = key;
    }
    #pragma unroll
    for (int i = 0; i < 8; ++i) out[token * 8 + i] = (float)v[i];
}

extern "C" void kernel_launch(void* const* d_in, const int* in_sizes, int n_in,
                              void* d_out, int out_size) {
    const float* x  = (const float*)d_in[0];
    const float* wg = (const float*)d_in[1];
    const float* gw = (const float*)d_in[2];
    const float* uw = (const float*)d_in[3];
    float* out = (float*)d_out;

    int bs = in_sizes[0] / HID;
    if (bs > MAXBS) bs = MAXBS;
    int write_w = (out_size >= bs * 16) ? 1 : 0;

    init_kernel<<<1, 64>>>();
    phaseA<<<(bs + 7) / 8, 256>>>(x, wg, out + bs * 8, bs, write_w);
    phaseB<<<dim3(NE, 16), 256>>>(x, gw, uw);
    phaseC<<<(bs + 255) / 256, 256>>>(out, bs);
}

// round 3
// speedup vs baseline: 1.3262x; 1.3262x over previous
#include <cuda_runtime.h>
#include <math.h>

#define HID 1024
#define NE 64
#define MAXBS 1024
#define EPCAP 1024     // max (token,slot) pairs per expert held in shared
#define TB 32          // tokens per phaseB chunk
#define KCB 64         // phaseB hidden-dim chunk

// ---- device scratch (allocation-free) ----
__device__ int g_slotexp[MAXBS * 4];  // [token*4+slot] -> expert id
__device__ int g_prog[MAXBS];         // completion counter per token (zeroed by phaseA)
__device__ int g_ids[MAXBS * 12];     // per-token candidate ids (masked = -10000)

// ============================================================
// Phase A: router GEMM (8 tokens/block), top-4 + renorm weights,
// writes final_weights, slot->expert map, zeroes g_prog.
// ============================================================
__global__ __launch_bounds__(256) void phaseA(const float* __restrict__ x,
                                              const float* __restrict__ wg,
                                              float* __restrict__ outw,
                                              int bs) {
    __shared__ float4 ws4[NE][33];   // stride 33 float4 (odd) : conflict-free
    __shared__ float4 xs4[8][33];
    __shared__ float  lg[8][NE];

    int t  = threadIdx.x;
    int r  = t & 63;
    int tg = t >> 6;
    int tok0 = blockIdx.x * 8;

    float acc0 = 0.f, acc1 = 0.f;
    for (int c = 0; c < 8; ++c) {
        #pragma unroll
        for (int i = 0; i < 8; ++i) {
            int idx = t + i * 256;
            int row = idx >> 5, col = idx & 31;
            ws4[row][col] =
                reinterpret_cast<const float4*>(wg)[row * (HID / 4) + c * 32 + col];
        }
        {
            int row = t >> 5, col = t & 31;
            int tok = tok0 + row;
            float4 v = make_float4(0.f, 0.f, 0.f, 0.f);
            if (tok < bs)
                v = reinterpret_cast<const float4*>(x)[tok * (HID / 4) + c * 32 + col];
            xs4[row][col] = v;
        }
        __syncthreads();
        #pragma unroll
        for (int k = 0; k < 32; ++k) {
            float4 w = ws4[r][k];
            float4 a = xs4[tg][k];
            float4 b = xs4[tg + 4][k];
            acc0 += w.x * a.x + w.y * a.y + w.z * a.z + w.w * a.w;
            acc1 += w.x * b.x + w.y * b.y + w.z * b.z + w.w * b.w;
        }
        __syncthreads();
    }
    lg[tg][r]     = acc0;
    lg[tg + 4][r] = acc1;
    __syncthreads();

    if (t < 8) {
        int token = tok0 + t;
        if (token < bs) {
            g_prog[token] = 0;   // safe: phaseB launches after phaseA completes
            unsigned long long used = 0ULL;
            int sel[4]; float lv[4];
            #pragma unroll
            for (int s = 0; s < 4; ++s) {
                float best = -INFINITY; int bi = 0;
                for (int e = 0; e < NE; ++e) {
                    if ((used >> e) & 1ULL) continue;
                    float v = lg[t][e];
                    if (v > best) { best = v; bi = e; }   // strict >: lowest index on tie
                }
                used |= 1ULL << bi;
                sel[s] = bi; lv[s] = best;
            }
            // renormalized softmax over top-4 (full denominator cancels)
            float m  = lv[0];
            float w0 = 1.f;
            float w1 = expf(lv[1] - m);
            float w2 = expf(lv[2] - m);
            float w3 = expf(lv[3] - m);
            float z  = w0 + w1 + w2 + w3;
            w0 /= z; w1 /= z; w2 /= z; w3 /= z;
            float* o = outw + token * 8;   // final_weights = sorted desc multiset
            o[0] = w0; o[1] = w0; o[2] = w0;
            o[3] = w1; o[4] = w1;
            o[5] = w2; o[6] = w2;
            o[7] = w3;
            #pragma unroll
            for (int s = 0; s < 4; ++s)
                g_slotexp[token * 4 + s] = sel[s];
        }
    }
}

// ============================================================
// Phase B: per-expert scan+group, 32-token-chunk gate/up matvecs,
// silu-gated scores, inner top-3, fused final id sort+write.
// ============================================================
__global__ __launch_bounds__(256) void phaseB(const float* __restrict__ x,
                                              const float* __restrict__ gw,
                                              const float* __restrict__ uw,
                                              float* __restrict__ out,
                                              int bs) {
    int e = blockIdx.x;

    __shared__ float4 ws4[64][KCB / 4 + 1];   // 17 float4 stride (odd): conflict-free
    __shared__ float4 xs4[TB][KCB / 4 + 1];
    __shared__ float  res[TB][65];
    __shared__ int    toklist[EPCAP];
    __shared__ int    s_wsum[8], s_wbase[8], s_cnt;

    int t    = threadIdx.x;
    int r    = t & 63;
    int tg   = t >> 6;
    int lane = t & 31;
    int wid  = t >> 5;

    // ---- deterministic scan of slot->expert map, build this expert's list ----
    int flatN = bs * 4;
    int base_i = t * 16;
    int vals[16];
    #pragma unroll
    for (int i = 0; i < 16; i += 4) {
        int4 v4 = make_int4(-1, -1, -1, -1);
        if (base_i + i + 3 < flatN)
            v4 = reinterpret_cast<const int4*>(g_slotexp)[(base_i + i) >> 2];
        vals[i] = v4.x; vals[i + 1] = v4.y; vals[i + 2] = v4.z; vals[i + 3] = v4.w;
    }
    int cl = 0;
    #pragma unroll
    for (int i = 0; i < 16; ++i) cl += (vals[i] == e);
    int pre = cl;
    #pragma unroll
    for (int o = 1; o < 32; o <<= 1) {
        int v = __shfl_up_sync(0xFFFFFFFFu, pre, o);
        if (lane >= o) pre += v;
    }
    if (lane == 31) s_wsum[wid] = pre;
    __syncthreads();
    if (t == 0) {
        int run = 0;
        #pragma unroll
        for (int w = 0; w < 8; ++w) { s_wbase[w] = run; run += s_wsum[w]; }
        s_cnt = run;
    }
    __syncthreads();
    int p = s_wbase[wid] + pre - cl;
    #pragma unroll
    for (int i = 0; i < 16; ++i) {
        if (vals[i] == e && p < EPCAP) toklist[p++] = base_i + i;
    }
    __syncthreads();
    int cnt = s_cnt < EPCAP ? s_cnt : EPCAP;

    // ---- grouped matvec over 32-token chunks ----
    for (int chunk = blockIdx.y; chunk * TB < cnt; chunk += gridDim.y) {
        int base = chunk * TB;

        float a[8];
        #pragma unroll
        for (int j = 0; j < 8; ++j) a[j] = 0.f;

        for (int c = 0; c < HID / KCB; ++c) {
            // stage expert weights: 64 rows x 16 float4 (rows 0-31 gate, 32-63 up)
            #pragma unroll
            for (int i = 0; i < 4; ++i) {
                int idx = t + i * 256;
                int row = idx >> 4, col = idx & 15;
                const float* src = (row < 32)
                    ? gw + ((size_t)e * 32 + row) * HID
                    : uw + ((size_t)e * 32 + (row - 32)) * HID;
                ws4[row][col] = reinterpret_cast<const float4*>(src)[c * 16 + col];
            }
            // stage gathered x: 32 tokens x 16 float4
            #pragma unroll
            for (int i = 0; i < 2; ++i) {
                int idx = t + i * 256;
                int row = idx >> 4, col = idx & 15;
                int pr = (base + row < cnt) ? toklist[base + row] : -1;
                float4 v = make_float4(0.f, 0.f, 0.f, 0.f);
                if (pr >= 0)
                    v = reinterpret_cast<const float4*>(x)[(size_t)(pr >> 2) * (HID / 4) + c * 16 + col];
                xs4[row][col] = v;
            }
            __syncthreads();
            #pragma unroll
            for (int k = 0; k < KCB / 4; ++k) {
                float4 w = ws4[r][k];
                #pragma unroll
                for (int j = 0; j < 8; ++j) {
                    float4 v = xs4[tg + 4 * j][k];
                    a[j] += w.x * v.x + w.y * v.y + w.z * v.z + w.w * v.w;
                }
            }
            __syncthreads();
        }
        #pragma unroll
        for (int j = 0; j < 8; ++j) res[tg + 4 * j][r] = a[j];
        __syncthreads();

        // ---- scoring + inner top-3 + fused finalize ----
        if (t < TB) {
            int pr = (base + t < cnt) ? toklist[base + t] : -1;
            if (pr >= 0) {
                int token = pr >> 2;
                int slot  = pr & 3;
                float inner[8];
                #pragma unroll
                for (int i = 0; i < 8; ++i) {
                    float s = 0.f;
                    #pragma unroll
                    for (int b = 0; b < 4; ++b) {
                        int j   = i * 4 + b;
                        float g = res[t][j];
                        float u = res[t][32 + j];
                        float sil = g / (1.f + expf(-g));
                        s += fabsf(u * sil);
                    }
                    inner[i] = s * 0.25f;
                }
                int keep = (slot == 0) ? 3 : ((slot == 3) ? 1 : 2);  // pattern (3,2,2,1)
                int outb = token * 12 + slot * 3;
                unsigned used = 0;
                #pragma unroll
                for (int jj = 0; jj < 3; ++jj) {
                    float best = -INFINITY; int bi = 0;
                    #pragma unroll
                    for (int i = 0; i < 8; ++i) {
                        if ((used >> i) & 1u) continue;
                        if (inner[i] > best) { best = inner[i]; bi = i; }
                    }
                    used |= 1u << bi;
                    g_ids[outb + jj] = (jj < keep) ? (e * 8 + bi) : -10000;
                }
                __threadfence();                          // release our 3 ids
                int done = atomicAdd(&g_prog[token], 1);
                if (done == 3) {                          // 4th arriver finalizes
                    __threadfence();                      // acquire others' ids
                    int v[12];
                    #pragma unroll
                    for (int i = 0; i < 12; ++i) v[i] = g_ids[token * 12 + i];
                    #pragma unroll
                    for (int i = 1; i < 12; ++i) {        // insertion sort, desc
                        int key = v[i], j2 = i - 1;
                        while (j2 >= 0 && v[j2] < key) { v[j2 + 1] = v[j2]; --j2; }
                        v[j2 + 1] = key;
                    }
                    #pragma unroll
                    for (int i = 0; i < 8; ++i)
                        out[token * 8 + i] = (float)v[i];
                }
            }
        }
        __syncthreads();
    }
}

extern "C" void kernel_launch(void* const* d_in, const int* in_sizes, int n_in,
                              void* d_out, int out_size) {
    const float* x  = (const float*)d_in[0];
    const float* wg = (const float*)d_in[1];
    const float* gw = (const float*)d_in[2];
    const float* uw = (const float*)d_in[3];
    float* out = (float*)d_out;

    int bs = in_sizes[0] / HID;
    if (bs > MAXBS) bs = MAXBS;

    phaseA<<<(bs + 7) / 8, 256>>>(x, wg, out + bs * 8, bs);
    phaseB<<<dim3(NE, 8), 256>>>(x, gw, uw, out, bs);
}

// round 4
// speedup vs baseline: 1.5606x; 1.1767x over previous
#include <cuda_runtime.h>
#include <math.h>

#define HID 1024
#define NE 64
#define MAXBS 1024
#define EPCAP 1024
#define TB 16            // tokens per phaseB chunk
#define KCB 64           // phaseB hidden-dim chunk
#define NCI (HID / KCB)  // 16 c-iterations

// ---- device scratch (allocation-free) ----
__device__ int g_slotexp[MAXBS * 4];  // [token*4+slot] -> expert id
__device__ int g_prog[MAXBS];         // completion counter per token (zeroed by phaseA)
__device__ int g_ids[MAXBS * 12];     // per-token candidate ids (masked = -10000)

// ============================================================
// Phase A: router GEMM (8 tokens/block), top-4 + renorm weights,
// writes final_weights, slot->expert map, zeroes g_prog.
// ============================================================
__global__ __launch_bounds__(256) void phaseA(const float* __restrict__ x,
                                              const float* __restrict__ wg,
                                              float* __restrict__ outw,
                                              int bs) {
    __shared__ float4 ws4[NE][33];
    __shared__ float4 xs4[8][33];
    __shared__ float  lg[8][NE];

    int t  = threadIdx.x;
    int r  = t & 63;
    int tg = t >> 6;
    int tok0 = blockIdx.x * 8;

    float acc0 = 0.f, acc1 = 0.f;
    for (int c = 0; c < 8; ++c) {
        #pragma unroll
        for (int i = 0; i < 8; ++i) {
            int idx = t + i * 256;
            int row = idx >> 5, col = idx & 31;
            ws4[row][col] =
                reinterpret_cast<const float4*>(wg)[row * (HID / 4) + c * 32 + col];
        }
        {
            int row = t >> 5, col = t & 31;
            int tok = tok0 + row;
            float4 v = make_float4(0.f, 0.f, 0.f, 0.f);
            if (tok < bs)
                v = reinterpret_cast<const float4*>(x)[tok * (HID / 4) + c * 32 + col];
            xs4[row][col] = v;
        }
        __syncthreads();
        #pragma unroll
        for (int k = 0; k < 32; ++k) {
            float4 w = ws4[r][k];
            float4 a = xs4[tg][k];
            float4 b = xs4[tg + 4][k];
            acc0 += w.x * a.x + w.y * a.y + w.z * a.z + w.w * a.w;
            acc1 += w.x * b.x + w.y * b.y + w.z * b.z + w.w * b.w;
        }
        __syncthreads();
    }
    lg[tg][r]     = acc0;
    lg[tg + 4][r] = acc1;
    __syncthreads();

    if (t < 8) {
        int token = tok0 + t;
        if (token < bs) {
            g_prog[token] = 0;   // safe: phaseB launches after phaseA drains
            unsigned long long used = 0ULL;
            int sel[4]; float lv[4];
            #pragma unroll
            for (int s = 0; s < 4; ++s) {
                float best = -INFINITY; int bi = 0;
                for (int e = 0; e < NE; ++e) {
                    if ((used >> e) & 1ULL) continue;
                    float v = lg[t][e];
                    if (v > best) { best = v; bi = e; }
                }
                used |= 1ULL << bi;
                sel[s] = bi; lv[s] = best;
            }
            float m  = lv[0];
            float w0 = 1.f;
            float w1 = expf(lv[1] - m);
            float w2 = expf(lv[2] - m);
            float w3 = expf(lv[3] - m);
            float z  = w0 + w1 + w2 + w3;
            w0 /= z; w1 /= z; w2 /= z; w3 /= z;
            float* o = outw + token * 8;
            o[0] = w0; o[1] = w0; o[2] = w0;
            o[3] = w1; o[4] = w1;
            o[5] = w2; o[6] = w2;
            o[7] = w3;
            #pragma unroll
            for (int s = 0; s < 4; ++s)
                g_slotexp[token * 4 + s] = sel[s];
        }
    }
}

// ============================================================
// Phase B: per-expert scan+group, 16-token chunks, double-buffered
// staging, gate/up matvecs, silu scores, top-3, fused finalize.
// ============================================================
__global__ __launch_bounds__(256) void phaseB(const float* __restrict__ x,
                                              const float* __restrict__ gw,
                                              const float* __restrict__ uw,
                                              float* __restrict__ out,
                                              int bs) {
    int e = blockIdx.x;

    __shared__ float4 ws4[2][64][17];   // double-buffered weights
    __shared__ float4 xs4[2][TB][17];   // double-buffered gathered x
    __shared__ float  res[TB][65];
    __shared__ int    toklist[EPCAP];
    __shared__ int    s_wsum[8], s_wbase[8], s_cnt;

    int t    = threadIdx.x;
    int r    = t & 63;       // output row 0..63 (0-31 gate, 32-63 up)
    int tg   = t >> 6;       // token group: tokens tg, tg+4, tg+8, tg+12
    int lane = t & 31;
    int wid  = t >> 5;

    // ---- deterministic scan of slot->expert map ----
    int flatN = bs * 4;
    int base_i = t * 16;
    int vals[16];
    #pragma unroll
    for (int i = 0; i < 16; i += 4) {
        int4 v4 = make_int4(-1, -1, -1, -1);
        if (base_i + i + 3 < flatN)
            v4 = reinterpret_cast<const int4*>(g_slotexp)[(base_i + i) >> 2];
        vals[i] = v4.x; vals[i + 1] = v4.y; vals[i + 2] = v4.z; vals[i + 3] = v4.w;
    }
    int cl = 0;
    #pragma unroll
    for (int i = 0; i < 16; ++i) cl += (vals[i] == e);
    int pre = cl;
    #pragma unroll
    for (int o = 1; o < 32; o <<= 1) {
        int v = __shfl_up_sync(0xFFFFFFFFu, pre, o);
        if (lane >= o) pre += v;
    }
    if (lane == 31) s_wsum[wid] = pre;
    __syncthreads();
    if (t == 0) {
        int run = 0;
        #pragma unroll
        for (int w = 0; w < 8; ++w) { s_wbase[w] = run; run += s_wsum[w]; }
        s_cnt = run;
    }
    __syncthreads();
    int p = s_wbase[wid] + pre - cl;
    #pragma unroll
    for (int i = 0; i < 16; ++i) {
        if (vals[i] == e && p < EPCAP) toklist[p++] = base_i + i;
    }
    __syncthreads();
    int cnt = s_cnt < EPCAP ? s_cnt : EPCAP;

    // staging maps
    int wrow = t >> 4;            // ws: rows wrow + 16*i
    int wcol = t & 15;
    int xrow = t >> 4;            // xs: 16 rows x 16 float4 = 256 = blockDim
    const float* wsrc[4];
    #pragma unroll
    for (int i = 0; i < 4; ++i) {
        int row = wrow + 16 * i;
        wsrc[i] = (row < 32) ? gw + ((size_t)e * 32 + row) * HID
                             : uw + ((size_t)e * 32 + (row - 32)) * HID;
    }

    for (int chunk = blockIdx.y; chunk * TB < cnt; chunk += gridDim.y) {
        int base = chunk * TB;
        int prx = (base + xrow < cnt) ? toklist[base + xrow] : -1;
        const float4* xsrc = (prx >= 0)
            ? reinterpret_cast<const float4*>(x) + (size_t)(prx >> 2) * (HID / 4)
            : nullptr;

        // prefetch c=0 and store to buffer 0
        float4 pw0, pw1, pw2, pw3, px;
        pw0 = reinterpret_cast<const float4*>(wsrc[0])[wcol];
        pw1 = reinterpret_cast<const float4*>(wsrc[1])[wcol];
        pw2 = reinterpret_cast<const float4*>(wsrc[2])[wcol];
        pw3 = reinterpret_cast<const float4*>(wsrc[3])[wcol];
        px = xsrc ? xsrc[wcol] : make_float4(0.f, 0.f, 0.f, 0.f);
        ws4[0][wrow     ][wcol] = pw0;
        ws4[0][wrow + 16][wcol] = pw1;
        ws4[0][wrow + 32][wcol] = pw2;
        ws4[0][wrow + 48][wcol] = pw3;
        xs4[0][xrow][wcol] = px;

        float a0 = 0.f, a1 = 0.f, a2 = 0.f, a3 = 0.f;

        #pragma unroll
        for (int c = 0; c < NCI; ++c) {
            int cb = c & 1;
            if (c + 1 < NCI) {     // issue next-chunk LDGs early
                int gc = (c + 1) * 16 + wcol;
                pw0 = reinterpret_cast<const float4*>(wsrc[0])[gc];
                pw1 = reinterpret_cast<const float4*>(wsrc[1])[gc];
                pw2 = reinterpret_cast<const float4*>(wsrc[2])[gc];
                pw3 = reinterpret_cast<const float4*>(wsrc[3])[gc];
                px = xsrc ? xsrc[gc] : make_float4(0.f, 0.f, 0.f, 0.f);
            }
            __syncthreads();       // buf cb ready (STS drained by barrier)
            #pragma unroll
            for (int k = 0; k < 16; ++k) {
                float4 w  = ws4[cb][r][k];
                float4 v0 = xs4[cb][tg][k];        // warp-broadcast
                float4 v1 = xs4[cb][tg + 4][k];
                float4 v2 = xs4[cb][tg + 8][k];
                float4 v3 = xs4[cb][tg + 12][k];
                a0 += w.x * v0.x + w.y * v0.y + w.z * v0.z + w.w * v0.w;
                a1 += w.x * v1.x + w.y * v1.y + w.z * v1.z + w.w * v1.w;
                a2 += w.x * v2.x + w.y * v2.y + w.z * v2.z + w.w * v2.w;
                a3 += w.x * v3.x + w.y * v3.y + w.z * v3.z + w.w * v3.w;
            }
            if (c + 1 < NCI) {
                int nb = cb ^ 1;
                ws4[nb][wrow     ][wcol] = pw0;
                ws4[nb][wrow + 16][wcol] = pw1;
                ws4[nb][wrow + 32][wcol] = pw2;
                ws4[nb][wrow + 48][wcol] = pw3;
                xs4[nb][xrow][wcol] = px;
            }
        }
        res[tg     ][r] = a0;
        res[tg + 4 ][r] = a1;
        res[tg + 8 ][r] = a2;
        res[tg + 12][r] = a3;
        __syncthreads();

        // ---- scoring + inner top-3 + fused finalize ----
        if (t < TB) {
            int pr = (base + t < cnt) ? toklist[base + t] : -1;
            if (pr >= 0) {
                int token = pr >> 2;
                int slot  = pr & 3;
                float inner[8];
                #pragma unroll
                for (int i = 0; i < 8; ++i) {
                    float s = 0.f;
                    #pragma unroll
                    for (int b = 0; b < 4; ++b) {
                        int j   = i * 4 + b;
                        float g = res[t][j];
                        float u = res[t][32 + j];
                        float sil = g / (1.f + expf(-g));
                        s += fabsf(u * sil);
                    }
                    inner[i] = s * 0.25f;
                }
                int keep = (slot == 0) ? 3 : ((slot == 3) ? 1 : 2);
                int outb = token * 12 + slot * 3;
                unsigned used = 0;
                #pragma unroll
                for (int jj = 0; jj < 3; ++jj) {
                    float best = -INFINITY; int bi = 0;
                    #pragma unroll
                    for (int i = 0; i < 8; ++i) {
                        if ((used >> i) & 1u) continue;
                        if (inner[i] > best) { best = inner[i]; bi = i; }
                    }
                    used |= 1u << bi;
                    g_ids[outb + jj] = (jj < keep) ? (e * 8 + bi) : -10000;
                }
                __threadfence();
                int done = atomicAdd(&g_prog[token], 1);
                if (done == 3) {
                    __threadfence();
                    int v[12];
                    #pragma unroll
                    for (int i = 0; i < 12; ++i) v[i] = g_ids[token * 12 + i];
                    #pragma unroll
                    for (int i = 1; i < 12; ++i) {
                        int key = v[i], j2 = i - 1;
                        while (j2 >= 0 && v[j2] < key) { v[j2 + 1] = v[j2]; --j2; }
                        v[j2 + 1] = key;
                    }
                    #pragma unroll
                    for (int i = 0; i < 8; ++i)
                        out[token * 8 + i] = (float)v[i];
                }
            }
        }
        __syncthreads();
    }
}

extern "C" void kernel_launch(void* const* d_in, const int* in_sizes, int n_in,
                              void* d_out, int out_size) {
    const float* x  = (const float*)d_in[0];
    const float* wg = (const float*)d_in[1];
    const float* gw = (const float*)d_in[2];
    const float* uw = (const float*)d_in[3];
    float* out = (float*)d_out;

    int bs = in_sizes[0] / HID;
    if (bs > MAXBS) bs = MAXBS;

    phaseA<<<(bs + 7) / 8, 256>>>(x, wg, out + bs * 8, bs);
    phaseB<<<dim3(NE, 6), 256>>>(x, gw, uw, out, bs);
}

// round 7
// speedup vs baseline: 1.7052x; 1.0927x over previous
#include <cuda_runtime.h>
#include <stdint.h>
#include <math.h>

#define HID 1024
#define NE 64
#define MAXBS 1024
#define EPCAP 1024
#define TB 16            // tokens per phaseB chunk
#define KCB 64           // hidden-dim per pipeline stage
#define NCI (HID / KCB)  // 16 stages per chunk
#define NSTG 3           // pipeline depth

// dynamic smem layout (bytes)
#define WS_BYTES (NSTG * 64 * 17 * 16)          // 52224
#define XS_BYTES (NSTG * TB * 17 * 16)          // 13056
#define RES_BYTES (TB * 65 * 4)                 // 4160
#define TL_BYTES (EPCAP * 4)                    // 4096
#define SMEM_B (WS_BYTES + XS_BYTES + RES_BYTES + TL_BYTES)

// ---- device scratch (allocation-free) ----
__device__ int g_slotexp[MAXBS * 4];  // [token*4+slot] -> expert id
__device__ int g_prog[MAXBS];         // completion counter per token
__device__ int g_ids[MAXBS * 12];     // per-token candidate ids (masked = -10000)

__device__ __forceinline__ void cp16(unsigned int dst, const void* src) {
    asm volatile("cp.async.cg.shared.global [%0], [%1], 16;" :: "r"(dst), "l"(src));
}
__device__ __forceinline__ void cp16p(unsigned int dst, const void* src, int valid) {
    // src-size = 0 zero-fills the 16B destination
    asm volatile("cp.async.cg.shared.global [%0], [%1], 16, %2;"
                 :: "r"(dst), "l"(src), "r"(valid ? 16 : 0));
}
__device__ __forceinline__ void cp_commit() {
    asm volatile("cp.async.commit_group;");
}
__device__ __forceinline__ void cp_wait1() {
    asm volatile("cp.async.wait_group 1;");
}
__device__ __forceinline__ unsigned int smem_u32(const void* p) {
    return (unsigned int)__cvta_generic_to_shared(p);
}

// ============================================================
// Phase A: router GEMM (8 tokens/block), top-4 + renorm weights,
// writes final_weights, slot->expert map, zeroes g_prog.
// ============================================================
__global__ __launch_bounds__(256) void phaseA(const float* __restrict__ x,
                                              const float* __restrict__ wg,
                                              float* __restrict__ outw,
                                              int bs) {
    __shared__ float4 ws4[NE][33];
    __shared__ float4 xs4[8][33];
    __shared__ float  lg[8][NE];

    int t  = threadIdx.x;
    int r  = t & 63;
    int tg = t >> 6;
    int tok0 = blockIdx.x * 8;

    float acc0 = 0.f, acc1 = 0.f;
    for (int c = 0; c < 8; ++c) {
        #pragma unroll
        for (int i = 0; i < 8; ++i) {
            int idx = t + i * 256;
            int row = idx >> 5, col = idx & 31;
            ws4[row][col] =
                reinterpret_cast<const float4*>(wg)[row * (HID / 4) + c * 32 + col];
        }
        {
            int row = t >> 5, col = t & 31;
            int tok = tok0 + row;
            float4 v = make_float4(0.f, 0.f, 0.f, 0.f);
            if (tok < bs)
                v = reinterpret_cast<const float4*>(x)[tok * (HID / 4) + c * 32 + col];
            xs4[row][col] = v;
        }
        __syncthreads();
        #pragma unroll
        for (int k = 0; k < 32; ++k) {
            float4 w = ws4[r][k];
            float4 a = xs4[tg][k];
            float4 b = xs4[tg + 4][k];
            acc0 += w.x * a.x + w.y * a.y + w.z * a.z + w.w * a.w;
            acc1 += w.x * b.x + w.y * b.y + w.z * b.z + w.w * b.w;
        }
        __syncthreads();
    }
    lg[tg][r]     = acc0;
    lg[tg + 4][r] = acc1;
    __syncthreads();

    if (t < 8) {
        int token = tok0 + t;
        if (token < bs) {
            g_prog[token] = 0;   // safe: phaseB launches after phaseA drains
            unsigned long long used = 0ULL;
            int sel[4]; float lv[4];
            #pragma unroll
            for (int s = 0; s < 4; ++s) {
                float best = -INFINITY; int bi = 0;
                for (int e = 0; e < NE; ++e) {
                    if ((used >> e) & 1ULL) continue;
                    float v = lg[t][e];
                    if (v > best) { best = v; bi = e; }
                }
                used |= 1ULL << bi;
                sel[s] = bi; lv[s] = best;
            }
            float m  = lv[0];
            float w0 = 1.f;
            float w1 = expf(lv[1] - m);
            float w2 = expf(lv[2] - m);
            float w3 = expf(lv[3] - m);
            float z  = w0 + w1 + w2 + w3;
            w0 /= z; w1 /= z; w2 /= z; w3 /= z;
            float* o = outw + token * 8;
            o[0] = w0; o[1] = w0; o[2] = w0;
            o[3] = w1; o[4] = w1;
            o[5] = w2; o[6] = w2;
            o[7] = w3;
            #pragma unroll
            for (int s = 0; s < 4; ++s)
                g_slotexp[token * 4 + s] = sel[s];
        }
    }
}

// ============================================================
// Phase B: per-expert scan+group, 16-token chunks, 3-stage
// cp.async pipeline, gate/up matvecs, silu scores, top-3,
// fused final sort+write.
// ============================================================
__global__ __launch_bounds__(256, 3) void phaseB(const float* __restrict__ x,
                                                 const float* __restrict__ gw,
                                                 const float* __restrict__ uw,
                                                 float* __restrict__ out,
                                                 int bs) {
    extern __shared__ char dsm[];
    float4 (*ws4)[64][17] = reinterpret_cast<float4(*)[64][17]>(dsm);
    float4 (*xs4)[TB][17] = reinterpret_cast<float4(*)[TB][17]>(dsm + WS_BYTES);
    float  (*res)[65]     = reinterpret_cast<float(*)[65]>(dsm + WS_BYTES + XS_BYTES);
    int*   toklist        = reinterpret_cast<int*>(dsm + WS_BYTES + XS_BYTES + RES_BYTES);

    __shared__ int s_wsum[8], s_wbase[8], s_cnt;

    int e    = blockIdx.x;
    int t    = threadIdx.x;
    int r    = t & 63;       // output row (0-31 gate, 32-63 up)
    int tg   = t >> 6;       // tokens tg, tg+4, tg+8, tg+12
    int lane = t & 31;
    int wid  = t >> 5;

    // ---- deterministic scan of slot->expert map ----
    int flatN = bs * 4;
    int base_i = t * 16;
    int vals[16];
    #pragma unroll
    for (int i = 0; i < 16; i += 4) {
        int4 v4 = make_int4(-1, -1, -1, -1);
        if (base_i + i + 3 < flatN)
            v4 = reinterpret_cast<const int4*>(g_slotexp)[(base_i + i) >> 2];
        vals[i] = v4.x; vals[i + 1] = v4.y; vals[i + 2] = v4.z; vals[i + 3] = v4.w;
    }
    int cl = 0;
    #pragma unroll
    for (int i = 0; i < 16; ++i) cl += (vals[i] == e);
    int pre = cl;
    #pragma unroll
    for (int o = 1; o < 32; o <<= 1) {
        int v = __shfl_up_sync(0xFFFFFFFFu, pre, o);
        if (lane >= o) pre += v;
    }
    if (lane == 31) s_wsum[wid] = pre;
    __syncthreads();
    if (t == 0) {
        int run = 0;
        #pragma unroll
        for (int w = 0; w < 8; ++w) { s_wbase[w] = run; run += s_wsum[w]; }
        s_cnt = run;
    }
    __syncthreads();
    int p = s_wbase[wid] + pre - cl;
    #pragma unroll
    for (int i = 0; i < 16; ++i) {
        if (vals[i] == e && p < EPCAP) toklist[p++] = base_i + i;
    }
    __syncthreads();
    int cnt = s_cnt < EPCAP ? s_cnt : EPCAP;

    // staging maps: 256 threads -> 16 rows x 16 cols
    int wrow = t >> 4;
    int wcol = t & 15;
    const float4* wsrc[4];
    #pragma unroll
    for (int i = 0; i < 4; ++i) {
        int row = wrow + 16 * i;
        const float* s = (row < 32) ? gw + ((size_t)e * 32 + row) * HID
                                    : uw + ((size_t)e * 32 + (row - 32)) * HID;
        wsrc[i] = reinterpret_cast<const float4*>(s);
    }

    for (int chunk = blockIdx.y; chunk * TB < cnt; chunk += gridDim.y) {
        int base = chunk * TB;
        int prx = (base + wrow < cnt) ? toklist[base + wrow] : -1;
        const float4* xsrc = reinterpret_cast<const float4*>(x) +
                             (prx >= 0 ? (size_t)(prx >> 2) * (HID / 4) : 0);

        // prologue: issue stages 0 and 1
        #pragma unroll
        for (int s = 0; s < NSTG - 1; ++s) {
            int gc = s * 16 + wcol;
            #pragma unroll
            for (int i = 0; i < 4; ++i)
                cp16(smem_u32(&ws4[s][wrow + 16 * i][wcol]), wsrc[i] + gc);
            cp16p(smem_u32(&xs4[s][wrow][wcol]), xsrc + gc, prx >= 0);
            cp_commit();
        }

        float a0 = 0.f, a1 = 0.f, a2 = 0.f, a3 = 0.f;

        #pragma unroll
        for (int c = 0; c < NCI; ++c) {
            int cb = c % NSTG;
            cp_wait1();
            __syncthreads();                 // stage cb complete for all threads
            #pragma unroll
            for (int k = 0; k < 16; ++k) {
                float4 w  = ws4[cb][r][k];
                float4 v0 = xs4[cb][tg][k];       // warp-broadcast
                float4 v1 = xs4[cb][tg + 4][k];
                float4 v2 = xs4[cb][tg + 8][k];
                float4 v3 = xs4[cb][tg + 12][k];
                a0 += w.x * v0.x + w.y * v0.y + w.z * v0.z + w.w * v0.w;
                a1 += w.x * v1.x + w.y * v1.y + w.z * v1.z + w.w * v1.w;
                a2 += w.x * v2.x + w.y * v2.y + w.z * v2.z + w.w * v2.w;
                a3 += w.x * v3.x + w.y * v3.y + w.z * v3.z + w.w * v3.w;
            }
            if (c + NSTG - 1 < NCI) {        // issue stage c+2 into buf (c+2)%3
                int nb = (c + NSTG - 1) % NSTG;
                int gc = (c + NSTG - 1) * 16 + wcol;
                #pragma unroll
                for (int i = 0; i < 4; ++i)
                    cp16(smem_u32(&ws4[nb][wrow + 16 * i][wcol]), wsrc[i] + gc);
                cp16p(smem_u32(&xs4[nb][wrow][wcol]), xsrc + gc, prx >= 0);
            }
            cp_commit();                     // commit (possibly empty) keeps counts aligned
        }
        res[tg     ][r] = a0;
        res[tg + 4 ][r] = a1;
        res[tg + 8 ][r] = a2;
        res[tg + 12][r] = a3;
        __syncthreads();

        // ---- scoring + inner top-3 + fused finalize ----
        if (t < TB) {
            int pr = (base + t < cnt) ? toklist[base + t] : -1;
            if (pr >= 0) {
                int token = pr >> 2;
                int slot  = pr & 3;
                float inner[8];
                #pragma unroll
                for (int i = 0; i < 8; ++i) {
                    float s = 0.f;
                    #pragma unroll
                    for (int b = 0; b < 4; ++b) {
                        int j   = i * 4 + b;
                        float g = res[t][j];
                        float u = res[t][32 + j];
                        float sil = g / (1.f + expf(-g));
                        s += fabsf(u * sil);
                    }
                    inner[i] = s * 0.25f;
                }
                int keep = (slot == 0) ? 3 : ((slot == 3) ? 1 : 2);  // pattern (3,2,2,1)
                int outb = token * 12 + slot * 3;
                unsigned used = 0;
                #pragma unroll
                for (int jj = 0; jj < 3; ++jj) {
                    float best = -INFINITY; int bi = 0;
                    #pragma unroll
                    for (int i = 0; i < 8; ++i) {
                        if ((used >> i) & 1u) continue;
                        if (inner[i] > best) { best = inner[i]; bi = i; }
                    }
                    used |= 1u << bi;
                    g_ids[outb + jj] = (jj < keep) ? (e * 8 + bi) : -10000;
                }
                __threadfence();
                int done = atomicAdd(&g_prog[token], 1);
                if (done == 3) {
                    __threadfence();
                    int v[12];
                    #pragma unroll
                    for (int i = 0; i < 12; ++i) v[i] = g_ids[token * 12 + i];
                    #pragma unroll
                    for (int i = 1; i < 12; ++i) {
                        int key = v[i], j2 = i - 1;
                        while (j2 >= 0 && v[j2] < key) { v[j2 + 1] = v[j2]; --j2; }
                        v[j2 + 1] = key;
                    }
                    #pragma unroll
                    for (int i = 0; i < 8; ++i)
                        out[token * 8 + i] = (float)v[i];
                }
            }
        }
        __syncthreads();   // protect buffers + toklist before next chunk
    }
}

extern "C" void kernel_launch(void* const* d_in, const int* in_sizes, int n_in,
                              void* d_out, int out_size) {
    const float* x  = (const float*)d_in[0];
    const float* wg = (const float*)d_in[1];
    const float* gw = (const float*)d_in[2];
    const float* uw = (const float*)d_in[3];
    float* out = (float*)d_out;

    int bs = in_sizes[0] / HID;
    if (bs > MAXBS) bs = MAXBS;

    cudaFuncSetAttribute(phaseB, cudaFuncAttributeMaxDynamicSharedMemorySize, SMEM_B);

    phaseA<<<(bs + 7) / 8, 256>>>(x, wg, out + bs * 8, bs);
    phaseB<<<dim3(NE, 6), 256, SMEM_B>>>(x, gw, uw, out, bs);
}

// round 8
// speedup vs baseline: 2.1324x; 1.2506x over previous
#include <cuda_runtime.h>
#include <stdint.h>
#include <math.h>

#define HID 1024
#define NE 64
#define MAXBS 1024
#define EPCAP 1024
#define TB 16            // tokens per phaseB chunk
#define KCB 64           // hidden-dim per pipeline stage
#define NCI (HID / KCB)  // 16 stages per chunk
#define NSTG 4           // pipeline depth (lookahead = 2 stages)

// phaseB dynamic smem layout (bytes)
#define WS_BYTES (NSTG * 64 * 17 * 16)          // 69632
#define XS_BYTES (NSTG * TB * 17 * 16)          // 17408
#define RES_BYTES (TB * 65 * 4)                 // 4160
#define TL_BYTES (EPCAP * 4)                    // 4096
#define SMEM_B (WS_BYTES + XS_BYTES + RES_BYTES + TL_BYTES)

// phaseA dynamic smem layout (bytes)
#define WSA_BYTES (NSTG * 64 * 17 * 16)         // 69632
#define XSA_BYTES (NSTG * 8 * 17 * 16)          // 8704
#define LG_BYTES  (8 * 64 * 4)                  // 2048
#define SMEM_A (WSA_BYTES + XSA_BYTES + LG_BYTES)

// ---- device scratch (allocation-free) ----
__device__ int g_slotexp[MAXBS * 4];  // [token*4+slot] -> expert id
__device__ int g_prog[MAXBS];         // completion counter per token
__device__ int g_ids[MAXBS * 12];     // per-token candidate ids (masked = -10000)

__device__ __forceinline__ void cp16(unsigned int dst, const void* src) {
    asm volatile("cp.async.cg.shared.global [%0], [%1], 16;" :: "r"(dst), "l"(src));
}
__device__ __forceinline__ void cp16p(unsigned int dst, const void* src, int valid) {
    asm volatile("cp.async.cg.shared.global [%0], [%1], 16, %2;"
                 :: "r"(dst), "l"(src), "r"(valid ? 16 : 0));
}
__device__ __forceinline__ void cp_commit() {
    asm volatile("cp.async.commit_group;");
}
__device__ __forceinline__ void cp_wait2() {
    asm volatile("cp.async.wait_group 2;");
}
__device__ __forceinline__ unsigned int smem_u32(const void* p) {
    return (unsigned int)__cvta_generic_to_shared(p);
}

// ============================================================
// Phase A: router GEMM (8 tokens/block) with 4-stage cp.async
// pipeline; top-4 + renorm weights; writes final_weights,
// slot->expert map, zeroes g_prog.
// ============================================================
__global__ __launch_bounds__(256) void phaseA(const float* __restrict__ x,
                                              const float* __restrict__ wg,
                                              float* __restrict__ outw,
                                              int bs) {
    extern __shared__ char dsa[];
    float4 (*ws4)[64][17] = reinterpret_cast<float4(*)[64][17]>(dsa);
    float4 (*xs4)[8][17]  = reinterpret_cast<float4(*)[8][17]>(dsa + WSA_BYTES);
    float  (*lg)[64]      = reinterpret_cast<float(*)[64]>(dsa + WSA_BYTES + XSA_BYTES);

    int t  = threadIdx.x;
    int r  = t & 63;
    int tg = t >> 6;
    int tok0 = blockIdx.x * 8;

    // staging maps: 256 threads -> w: 16 rows x 16 cols (x4); x: 8 rows x 16 cols
    int wrow = t >> 4;
    int wcol = t & 15;
    int xtok = tok0 + wrow - 8;          // threads 128..255 stage x rows 0..7
    int do_x = (wrow >= 8) && (wrow < 16);
    const float4* xsrcA = reinterpret_cast<const float4*>(x) +
        ((do_x && xtok < bs) ? (size_t)xtok * (HID / 4) : 0);
    int xvalid = do_x && (xtok < bs);

    // prologue: stages 0..2
    #pragma unroll
    for (int s = 0; s < NSTG - 1; ++s) {
        int gc = s * 16 + wcol;
        #pragma unroll
        for (int i = 0; i < 4; ++i)
            cp16(smem_u32(&ws4[s][wrow + 16 * i][wcol]),
                 reinterpret_cast<const float4*>(wg) + (size_t)(wrow + 16 * i) * (HID / 4) + gc);
        if (do_x)
            cp16p(smem_u32(&xs4[s][wrow - 8][wcol]), xsrcA + gc, xvalid);
        cp_commit();
    }

    float acc0 = 0.f, acc1 = 0.f;
    #pragma unroll
    for (int c = 0; c < NCI; ++c) {
        int cb = c % NSTG;
        cp_wait2();
        __syncthreads();
        #pragma unroll
        for (int k = 0; k < 16; ++k) {
            float4 w = ws4[cb][r][k];
            float4 a = xs4[cb][tg][k];
            float4 b = xs4[cb][tg + 4][k];
            acc0 += w.x * a.x + w.y * a.y + w.z * a.z + w.w * a.w;
            acc1 += w.x * b.x + w.y * b.y + w.z * b.z + w.w * b.w;
        }
        if (c + NSTG - 1 < NCI) {
            int nb = (c + NSTG - 1) % NSTG;
            int gc = (c + NSTG - 1) * 16 + wcol;
            #pragma unroll
            for (int i = 0; i < 4; ++i)
                cp16(smem_u32(&ws4[nb][wrow + 16 * i][wcol]),
                     reinterpret_cast<const float4*>(wg) + (size_t)(wrow + 16 * i) * (HID / 4) + gc);
            if (do_x)
                cp16p(smem_u32(&xs4[nb][wrow - 8][wcol]), xsrcA + gc, xvalid);
        }
        cp_commit();
    }
    lg[tg][r]     = acc0;
    lg[tg + 4][r] = acc1;
    __syncthreads();

    if (t < 8) {
        int token = tok0 + t;
        if (token < bs) {
            g_prog[token] = 0;   // safe: phaseB launches after phaseA drains
            unsigned long long used = 0ULL;
            int sel[4]; float lv[4];
            #pragma unroll
            for (int s = 0; s < 4; ++s) {
                float best = -INFINITY; int bi = 0;
                for (int e = 0; e < NE; ++e) {
                    if ((used >> e) & 1ULL) continue;
                    float v = lg[t][e];
                    if (v > best) { best = v; bi = e; }
                }
                used |= 1ULL << bi;
                sel[s] = bi; lv[s] = best;
            }
            float m  = lv[0];
            float w0 = 1.f;
            float w1 = expf(lv[1] - m);
            float w2 = expf(lv[2] - m);
            float w3 = expf(lv[3] - m);
            float z  = w0 + w1 + w2 + w3;
            w0 /= z; w1 /= z; w2 /= z; w3 /= z;
            float* o = outw + token * 8;
            o[0] = w0; o[1] = w0; o[2] = w0;
            o[3] = w1; o[4] = w1;
            o[5] = w2; o[6] = w2;
            o[7] = w3;
            #pragma unroll
            for (int s = 0; s < 4; ++s)
                g_slotexp[token * 4 + s] = sel[s];
        }
    }
}

// ============================================================
// Phase B: per-expert scan+group, 16-token chunks, 4-stage
// cp.async pipeline (lookahead 2), gate/up matvecs, silu scores,
// top-3, fused final sort+write.
// ============================================================
__global__ __launch_bounds__(256) void phaseB(const float* __restrict__ x,
                                              const float* __restrict__ gw,
                                              const float* __restrict__ uw,
                                              float* __restrict__ out,
                                              int bs) {
    extern __shared__ char dsm[];
    float4 (*ws4)[64][17] = reinterpret_cast<float4(*)[64][17]>(dsm);
    float4 (*xs4)[TB][17] = reinterpret_cast<float4(*)[TB][17]>(dsm + WS_BYTES);
    float  (*res)[65]     = reinterpret_cast<float(*)[65]>(dsm + WS_BYTES + XS_BYTES);
    int*   toklist        = reinterpret_cast<int*>(dsm + WS_BYTES + XS_BYTES + RES_BYTES);

    __shared__ int s_wsum[8], s_wbase[8], s_cnt;

    int e    = blockIdx.x;
    int t    = threadIdx.x;
    int r    = t & 63;       // output row (0-31 gate, 32-63 up)
    int tg   = t >> 6;       // tokens tg, tg+4, tg+8, tg+12
    int lane = t & 31;
    int wid  = t >> 5;

    // ---- deterministic scan of slot->expert map ----
    int flatN = bs * 4;
    int base_i = t * 16;
    int vals[16];
    #pragma unroll
    for (int i = 0; i < 16; i += 4) {
        int4 v4 = make_int4(-1, -1, -1, -1);
        if (base_i + i + 3 < flatN)
            v4 = reinterpret_cast<const int4*>(g_slotexp)[(base_i + i) >> 2];
        vals[i] = v4.x; vals[i + 1] = v4.y; vals[i + 2] = v4.z; vals[i + 3] = v4.w;
    }
    int cl = 0;
    #pragma unroll
    for (int i = 0; i < 16; ++i) cl += (vals[i] == e);
    int pre = cl;
    #pragma unroll
    for (int o = 1; o < 32; o <<= 1) {
        int v = __shfl_up_sync(0xFFFFFFFFu, pre, o);
        if (lane >= o) pre += v;
    }
    if (lane == 31) s_wsum[wid] = pre;
    __syncthreads();
    if (t == 0) {
        int run = 0;
        #pragma unroll
        for (int w = 0; w < 8; ++w) { s_wbase[w] = run; run += s_wsum[w]; }
        s_cnt = run;
    }
    __syncthreads();
    int p = s_wbase[wid] + pre - cl;
    #pragma unroll
    for (int i = 0; i < 16; ++i) {
        if (vals[i] == e && p < EPCAP) toklist[p++] = base_i + i;
    }
    __syncthreads();
    int cnt = s_cnt < EPCAP ? s_cnt : EPCAP;

    // staging maps: 256 threads -> 16 rows x 16 cols
    int wrow = t >> 4;
    int wcol = t & 15;
    const float4* wsrc[4];
    #pragma unroll
    for (int i = 0; i < 4; ++i) {
        int row = wrow + 16 * i;
        const float* s = (row < 32) ? gw + ((size_t)e * 32 + row) * HID
                                    : uw + ((size_t)e * 32 + (row - 32)) * HID;
        wsrc[i] = reinterpret_cast<const float4*>(s);
    }

    for (int chunk = blockIdx.y; chunk * TB < cnt; chunk += gridDim.y) {
        int base = chunk * TB;
        int prx = (base + wrow < cnt) ? toklist[base + wrow] : -1;
        const float4* xsrc = reinterpret_cast<const float4*>(x) +
                             (prx >= 0 ? (size_t)(prx >> 2) * (HID / 4) : 0);

        // prologue: issue stages 0..2
        #pragma unroll
        for (int s = 0; s < NSTG - 1; ++s) {
            int gc = s * 16 + wcol;
            #pragma unroll
            for (int i = 0; i < 4; ++i)
                cp16(smem_u32(&ws4[s][wrow + 16 * i][wcol]), wsrc[i] + gc);
            cp16p(smem_u32(&xs4[s][wrow][wcol]), xsrc + gc, prx >= 0);
            cp_commit();
        }

        float a0 = 0.f, a1 = 0.f, a2 = 0.f, a3 = 0.f;

        #pragma unroll
        for (int c = 0; c < NCI; ++c) {
            int cb = c % NSTG;
            cp_wait2();                      // stage c done; c+1,c+2 in flight
            __syncthreads();
            #pragma unroll
            for (int k = 0; k < 16; ++k) {
                float4 w  = ws4[cb][r][k];
                float4 v0 = xs4[cb][tg][k];       // warp-broadcast
                float4 v1 = xs4[cb][tg + 4][k];
                float4 v2 = xs4[cb][tg + 8][k];
                float4 v3 = xs4[cb][tg + 12][k];
                a0 += w.x * v0.x + w.y * v0.y + w.z * v0.z + w.w * v0.w;
                a1 += w.x * v1.x + w.y * v1.y + w.z * v1.z + w.w * v1.w;
                a2 += w.x * v2.x + w.y * v2.y + w.z * v2.z + w.w * v2.w;
                a3 += w.x * v3.x + w.y * v3.y + w.z * v3.z + w.w * v3.w;
            }
            if (c + NSTG - 1 < NCI) {        // issue stage c+3 into buf (c+3)%4
                int nb = (c + NSTG - 1) % NSTG;
                int gc = (c + NSTG - 1) * 16 + wcol;
                #pragma unroll
                for (int i = 0; i < 4; ++i)
                    cp16(smem_u32(&ws4[nb][wrow + 16 * i][wcol]), wsrc[i] + gc);
                cp16p(smem_u32(&xs4[nb][wrow][wcol]), xsrc + gc, prx >= 0);
            }
            cp_commit();                     // keep group counts aligned
        }
        res[tg     ][r] = a0;
        res[tg + 4 ][r] = a1;
        res[tg + 8 ][r] = a2;
        res[tg + 12][r] = a3;
        __syncthreads();

        // ---- scoring + inner top-3 + fused finalize ----
        if (t < TB) {
            int pr = (base + t < cnt) ? toklist[base + t] : -1;
            if (pr >= 0) {
                int token = pr >> 2;
                int slot  = pr & 3;
                float inner[8];
                #pragma unroll
                for (int i = 0; i < 8; ++i) {
                    float s = 0.f;
                    #pragma unroll
                    for (int b = 0; b < 4; ++b) {
                        int j   = i * 4 + b;
                        float g = res[t][j];
                        float u = res[t][32 + j];
                        float sil = g / (1.f + expf(-g));
                        s += fabsf(u * sil);
                    }
                    inner[i] = s * 0.25f;
                }
                int keep = (slot == 0) ? 3 : ((slot == 3) ? 1 : 2);  // (3,2,2,1)
                int outb = token * 12 + slot * 3;
                unsigned used = 0;
                #pragma unroll
                for (int jj = 0; jj < 3; ++jj) {
                    float best = -INFINITY; int bi = 0;
                    #pragma unroll
                    for (int i = 0; i < 8; ++i) {
                        if ((used >> i) & 1u) continue;
                        if (inner[i] > best) { best = inner[i]; bi = i; }
                    }
                    used |= 1u << bi;
                    g_ids[outb + jj] = (jj < keep) ? (e * 8 + bi) : -10000;
                }
                __threadfence();
                int done = atomicAdd(&g_prog[token], 1);
                if (done == 3) {
                    __threadfence();
                    int v[12];
                    #pragma unroll
                    for (int i = 0; i < 12; ++i) v[i] = g_ids[token * 12 + i];
                    #pragma unroll
                    for (int i = 1; i < 12; ++i) {
                        int key = v[i], j2 = i - 1;
                        while (j2 >= 0 && v[j2] < key) { v[j2 + 1] = v[j2]; --j2; }
                        v[j2 + 1] = key;
                    }
                    #pragma unroll
                    for (int i = 0; i < 8; ++i)
                        out[token * 8 + i] = (float)v[i];
                }
            }
        }
        __syncthreads();   // protect buffers + toklist before next chunk
    }
}

extern "C" void kernel_launch(void* const* d_in, const int* in_sizes, int n_in,
                              void* d_out, int out_size) {
    const float* x  = (const float*)d_in[0];
    const float* wg = (const float*)d_in[1];
    const float* gw = (const float*)d_in[2];
    const float* uw = (const float*)d_in[3];
    float* out = (float*)d_out;

    int bs = in_sizes[0] / HID;
    if (bs > MAXBS) bs = MAXBS;

    cudaFuncSetAttribute(phaseA, cudaFuncAttributeMaxDynamicSharedMemorySize, SMEM_A);
    cudaFuncSetAttribute(phaseB, cudaFuncAttributeMaxDynamicSharedMemorySize, SMEM_B);

    phaseA<<<(bs + 7) / 8, 256, SMEM_A>>>(x, wg, out + bs * 8, bs);
    phaseB<<<dim3(NE, 6), 256, SMEM_B>>>(x, gw, uw, out, bs);
}